// round 7
// baseline (speedup 1.0000x reference)
#include <cuda_runtime.h>
#include <cuda_bf16.h>
#include <cstdint>

#define B4 4096
#define N2 8192
#define DZ 128
#define DF 2048
#define LCOLS 8191

// output layout (float32): loss[1], logits[8192*8191], labels[8192], lids_k32[8192], lids_k512[8192]
#define OUT_LOSS    0ull
#define OUT_LOGITS  1ull
#define OUT_LABELS  (1ull + (unsigned long long)N2 * LCOLS)
#define OUT_LIDS32  (OUT_LABELS + N2)
#define OUT_LIDS512 (OUT_LIDS32 + N2)

// scratch (device globals: allocation-free per harness rules)
__device__ signed char g_fa[(size_t)N2 * DF];   // int8 plane a of f
__device__ signed char g_fb[(size_t)N2 * DF];   // int8 plane b of f
__device__ float g_ds[N2];                      // per-row quant scale delta
__device__ __nv_bfloat16 g_zhi[N2 * DZ];
__device__ __nv_bfloat16 g_zlo[N2 * DZ];
__device__ float g_fn[N2];                      // exact fp32 squared norms
__device__ float g_D[(size_t)N2 * N2];          // 256 MiB
__device__ float g_ls[64 * N2];                 // per-(tile-slot,row) exp partial sums
__device__ float g_lossper[N2];

// ---------------------------------------------------------------------------
// PTX helpers (plain sm_103-safe: mma.sync / ldmatrix / cp.async only)
// ---------------------------------------------------------------------------
__device__ __forceinline__ uint32_t smem_u32(const void* p) {
    uint32_t a;
    asm("{ .reg .u64 t; cvta.to.shared.u64 t, %1; cvt.u32.u64 %0, t; }" : "=r"(a) : "l"(p));
    return a;
}

#define CP_ASYNC16(dst, src) \
    asm volatile("cp.async.cg.shared.global [%0], [%1], 16;" :: "r"(dst), "l"(src) : "memory")
#define CP_COMMIT() asm volatile("cp.async.commit_group;" ::: "memory")
#define CP_WAIT1()  asm volatile("cp.async.wait_group 1;" ::: "memory")
#define CP_WAIT0()  asm volatile("cp.async.wait_group 0;" ::: "memory")

#define LDSM4(r, addr) \
    asm volatile("ldmatrix.sync.aligned.m8n8.x4.shared.b16 {%0,%1,%2,%3}, [%4];" \
        : "=r"((r)[0]), "=r"((r)[1]), "=r"((r)[2]), "=r"((r)[3]) : "r"(addr))

#define MMA16816(d, a, b0, b1) \
    asm volatile("mma.sync.aligned.m16n8k16.row.col.f32.bf16.bf16.f32 " \
        "{%0,%1,%2,%3}, {%4,%5,%6,%7}, {%8,%9}, {%0,%1,%2,%3};" \
        : "+f"((d)[0]), "+f"((d)[1]), "+f"((d)[2]), "+f"((d)[3]) \
        : "r"((a)[0]), "r"((a)[1]), "r"((a)[2]), "r"((a)[3]), "r"(b0), "r"(b1))

#define MMAI8(d, a, b0, b1) \
    asm volatile("mma.sync.aligned.m16n8k32.row.col.s32.s8.s8.s32 " \
        "{%0,%1,%2,%3}, {%4,%5,%6,%7}, {%8,%9}, {%0,%1,%2,%3};" \
        : "+r"((d)[0]), "+r"((d)[1]), "+r"((d)[2]), "+r"((d)[3]) \
        : "r"((a)[0]), "r"((a)[1]), "r"((a)[2]), "r"((a)[3]), "r"(b0), "r"(b1))

// off-diag column mapping (row gi, logical col gj) -> packed col, -1 = diag
__device__ __forceinline__ int colmap(int gi, int gj) {
    if (gi < B4) {
        if (gj >= B4) return gj - B4;
        if (gj == gi) return -1;
        return B4 + gj - (gj > gi ? 1 : 0);
    } else {
        if (gj < B4) return gj;
        if (gj == gi) return -1;
        return gj - (gj > gi ? 1 : 0);
    }
}

// ---------------------------------------------------------------------------
// prep: f exact norms + two-plane int8 quant; z normalize + bf16 split; labels
// ---------------------------------------------------------------------------
__global__ void __launch_bounds__(256) prep_kernel(
    const float* __restrict__ z0, const float* __restrict__ z1,
    const float* __restrict__ f0, const float* __restrict__ f1,
    float* __restrict__ out)
{
    int r = blockIdx.x;
    int tid = threadIdx.x;
    __shared__ float sred[256];
    __shared__ float smx[256];
    __shared__ float s_inv, s_del;

    const float* f = (r < B4) ? (f0 + (size_t)r * DF) : (f1 + (size_t)(r - B4) * DF);
    float s = 0.f, mx = 0.f;
    for (int j = tid; j < DF; j += 256) {
        float v = f[j];
        s += v * v;
        mx = fmaxf(mx, fabsf(v));
    }
    sred[tid] = s; smx[tid] = mx; __syncthreads();
    for (int st = 128; st > 0; st >>= 1) {
        if (tid < st) {
            sred[tid] += sred[tid + st];
            smx[tid] = fmaxf(smx[tid], smx[tid + st]);
        }
        __syncthreads();
    }
    if (tid == 0) {
        g_fn[r] = sred[0];
        float del = fmaxf(smx[0], 1e-30f) / 127.0f;
        g_ds[r] = del;
        s_del = del;
        s_inv = 1.0f / del;
    }
    __syncthreads();

    // two-plane int8 quantization: x ~= del*(a + b/128)
    {
        const float inv = s_inv, del = s_del;
        for (int base = tid * 8; base < tid * 8 + 8; base += 4) {
            float4 v = *(const float4*)&f[base];
            float x0 = v.x, x1 = v.y, x2 = v.z, x3 = v.w;
            int a0 = __float2int_rn(x0 * inv), a1 = __float2int_rn(x1 * inv);
            int a2 = __float2int_rn(x2 * inv), a3 = __float2int_rn(x3 * inv);
            int b0 = __float2int_rn((x0 - (float)a0 * del) * inv * 128.f);
            int b1 = __float2int_rn((x1 - (float)a1 * del) * inv * 128.f);
            int b2 = __float2int_rn((x2 - (float)a2 * del) * inv * 128.f);
            int b3 = __float2int_rn((x3 - (float)a3 * del) * inv * 128.f);
            *(char4*)&g_fa[(size_t)r * DF + base] =
                make_char4((signed char)a0, (signed char)a1, (signed char)a2, (signed char)a3);
            *(char4*)&g_fb[(size_t)r * DF + base] =
                make_char4((signed char)b0, (signed char)b1, (signed char)b2, (signed char)b3);
        }
    }

    const float* z = (r < B4) ? (z0 + (size_t)r * DZ) : (z1 + (size_t)(r - B4) * DZ);
    float v = (tid < DZ) ? z[tid] : 0.f;
    sred[tid] = v * v; __syncthreads();
    for (int st = 128; st > 0; st >>= 1) { if (tid < st) sred[tid] += sred[tid + st]; __syncthreads(); }
    float inv = 1.f / fmaxf(sqrtf(sred[0]), 1e-12f);
    if (tid < DZ) {
        float zn = v * inv;
        __nv_bfloat16 h = __float2bfloat16(zn);
        g_zhi[(size_t)r * DZ + tid] = h;
        g_zlo[(size_t)r * DZ + tid] = __float2bfloat16(zn - __bfloat162float(h));
    }
    if (tid == 0) out[OUT_LABELS + r] = (float)(r & (B4 - 1));
}

// ===========================================================================
// logits GEMM (K=128, split-bf16): CTA 128x128, warp 32x64, 2-stage.
// Triangle bc>=br, mirror via stride-129 smem transpose + off-diag scatter.
// Fused softmax-denominator partials (exp once; row sums + col sums).
// ===========================================================================
#define LSTAGE 40960              // Ah 10240 | Al 10240 | Bh 10240 | Bl 10240
#define ROWB 80                   // 64B data + 16B pad (LDSM conflict-free)
#define LSMEM_DYN (2 * LSTAGE)

__device__ __forceinline__ void load_stage_l(
    uint32_t sb, const __nv_bfloat16* __restrict__ hi, const __nv_bfloat16* __restrict__ lo,
    int aBase, int bBase, int kt)
{
    int tid = threadIdx.x;
    #pragma unroll
    for (int p = 0; p < 2; p++) {
        int c = tid + p * 256;
        int row = c >> 2, ch = c & 3;
        size_t offA = (size_t)(aBase + row) * DZ + kt + ch * 8;
        size_t offB = (size_t)(bBase + row) * DZ + kt + ch * 8;
        uint32_t d = sb + row * ROWB + ch * 16;
        CP_ASYNC16(d,         hi + offA);
        CP_ASYNC16(d + 10240, lo + offA);
        CP_ASYNC16(d + 20480, hi + offB);
        CP_ASYNC16(d + 30720, lo + offB);
    }
}

__global__ void __launch_bounds__(256, 1) logits_gemm_kernel(float* __restrict__ out)
{
    const int bc = blockIdx.x, br = blockIdx.y;
    if (bc < br) return;

    extern __shared__ char smem[];
    uint32_t sb = smem_u32(smem);
    const int tid = threadIdx.x, wid = tid >> 5, lane = tid & 31;
    const int aBase = br * 128, bBase = bc * 128;
    const int warpM = (wid & 3) * 32, warpN = (wid >> 2) * 64;

    const __nv_bfloat16* hi = &g_zhi[0];
    const __nv_bfloat16* lo = &g_zlo[0];

    float acc[2][8][4];
    #pragma unroll
    for (int m = 0; m < 2; m++)
        #pragma unroll
        for (int j = 0; j < 8; j++)
            #pragma unroll
            for (int q = 0; q < 4; q++) acc[m][j][q] = 0.f;

    const int aRow = lane & 15, aChunk = (lane >> 4) & 1;
    const int bRow = (lane & 7) | ((lane & 16) >> 1);
    const int bChunk = (lane >> 3) & 1;

    load_stage_l(sb, hi, lo, aBase, bBase, 0);
    CP_COMMIT();

    const int NK = DZ / 32;
    for (int it = 0; it < NK; it++) {
        const int s = it & 1;
        if (it + 1 < NK) {
            load_stage_l(sb + (s ^ 1) * LSTAGE, hi, lo, aBase, bBase, (it + 1) * 32);
            CP_COMMIT();
            CP_WAIT1();
        } else {
            CP_WAIT0();
        }
        __syncthreads();

        const uint32_t Ab = sb + s * LSTAGE;
        const uint32_t Bb = Ab + 20480;
        #pragma unroll
        for (int ks = 0; ks < 2; ks++) {
            uint32_t ah[2][4], al[2][4], bh[4][4], bl[4][4];
            uint32_t aAddr = Ab + (warpM + aRow) * ROWB + ks * 32 + aChunk * 16;
            LDSM4(ah[0], aAddr);
            LDSM4(ah[1], aAddr + 16 * ROWB);
            LDSM4(al[0], aAddr + 10240);
            LDSM4(al[1], aAddr + 10240 + 16 * ROWB);
            uint32_t bAddr = Bb + (warpN + bRow) * ROWB + ks * 32 + bChunk * 16;
            #pragma unroll
            for (int nt = 0; nt < 4; nt++) {
                LDSM4(bh[nt], bAddr + nt * 16 * ROWB);
                LDSM4(bl[nt], bAddr + 10240 + nt * 16 * ROWB);
            }
            #pragma unroll
            for (int mt = 0; mt < 2; mt++)
                #pragma unroll
                for (int j = 0; j < 8; j++) {
                    const int nt = j >> 1, hf = (j & 1) * 2;
                    MMA16816(acc[mt][j], ah[mt], bh[nt][hf], bh[nt][hf + 1]);
                    MMA16816(acc[mt][j], ah[mt], bl[nt][hf], bl[nt][hf + 1]);
                    MMA16816(acc[mt][j], al[mt], bh[nt][hf], bh[nt][hf + 1]);
                }
        }
        __syncthreads();
    }

    float* st = (float*)smem;
    #pragma unroll
    for (int mt = 0; mt < 2; mt++) {
        const int r0 = warpM + mt * 16 + (lane >> 2);
        #pragma unroll
        for (int j = 0; j < 8; j++) {
            const int c0 = warpN + (j >> 1) * 16 + (j & 1) * 8 + 2 * (lane & 3);
            #pragma unroll
            for (int q = 0; q < 4; q++)
                st[(r0 + (q >> 1) * 8) * 129 + c0 + (q & 1)] = 2.f * acc[mt][j][q];
        }
    }
    __syncthreads();

    for (int x = tid; x < 128 * 128; x += 256) {
        int mm = x >> 7, cc = x & 127;
        int col = colmap(aBase + mm, bBase + cc);
        if (col >= 0) out[OUT_LOGITS + (size_t)(aBase + mm) * LCOLS + col] = st[mm * 129 + cc];
    }
    if (bc > br) {
        for (int x = tid; x < 128 * 128; x += 256) {
            int rc = x >> 7, cm = x & 127;
            int col = colmap(bBase + rc, aBase + cm);
            if (col >= 0) out[OUT_LOGITS + (size_t)(bBase + rc) * LCOLS + col] = st[cm * 129 + rc];
        }
    }
    __syncthreads();

    // ---- fused exp + row/col partial sums (symmetry: triangle tiles only) ----
    for (int x = tid; x < 128 * 128; x += 256) {
        int mm = x >> 7, cc = x & 127;
        float e = __expf(st[mm * 129 + cc]);
        if (br == bc && mm == cc) e = 0.f;     // exclude diagonal
        st[mm * 129 + cc] = e;
    }
    __syncthreads();

    {   // row sums -> slot bc, rows aBase..aBase+127 (2 threads per row)
        int row = tid >> 1, half = tid & 1;
        float s = 0.f;
        #pragma unroll 4
        for (int c2 = half * 64; c2 < half * 64 + 64; c2++) s += st[row * 129 + c2];
        s += __shfl_xor_sync(0xFFFFFFFFu, s, 1);
        if (half == 0) g_ls[(size_t)bc * N2 + aBase + row] = s;
    }
    if (bc > br) {   // col sums -> slot br, rows bBase..bBase+127
        int col = tid >> 1, half = tid & 1;
        float s = 0.f;
        #pragma unroll 4
        for (int r2 = half * 64; r2 < half * 64 + 64; r2++) s += st[r2 * 129 + col];
        s += __shfl_xor_sync(0xFFFFFFFFu, s, 1);
        if (half == 0) g_ls[(size_t)br * N2 + bBase + col] = s;
    }
}

// ---------------------------------------------------------------------------
// loss_final: per row, S = sum of 64 partials; pos = 2*dot(z0n, z1n)
// ---------------------------------------------------------------------------
__global__ void __launch_bounds__(128) loss_final_kernel()
{
    int r = blockIdx.x, tid = threadIdx.x;
    int pr = (r < B4) ? r + B4 : r - B4;

    float a = (float)g_zhi[(size_t)r * DZ + tid] + (float)g_zlo[(size_t)r * DZ + tid];
    float b = (float)g_zhi[(size_t)pr * DZ + tid] + (float)g_zlo[(size_t)pr * DZ + tid];
    float p = a * b;
    float S = (tid < 64) ? g_ls[(size_t)tid * N2 + r] : 0.f;

    #pragma unroll
    for (int d = 16; d > 0; d >>= 1) {
        p += __shfl_xor_sync(0xFFFFFFFFu, p, d);
        S += __shfl_xor_sync(0xFFFFFFFFu, S, d);
    }
    __shared__ float sp[4], sS[4];
    if ((tid & 31) == 0) { sp[tid >> 5] = p; sS[tid >> 5] = S; }
    __syncthreads();
    if (tid == 0) {
        float P = sp[0] + sp[1] + sp[2] + sp[3];
        float SS = sS[0] + sS[1] + sS[2] + sS[3];
        g_lossper[r] = logf(SS) - 2.f * P;
    }
}

__global__ void __launch_bounds__(256) finalize_kernel(float* __restrict__ out)
{
    __shared__ double sred[256];
    int tid = threadIdx.x;
    double s = 0.0;
    for (int j = tid; j < N2; j += 256) s += (double)g_lossper[j];
    sred[tid] = s; __syncthreads();
    for (int st = 128; st > 0; st >>= 1) { if (tid < st) sred[tid] += sred[tid + st]; __syncthreads(); }
    if (tid == 0) out[OUT_LOSS] = (float)(sred[0] / (double)N2);
}

// ===========================================================================
// dist GEMM (K=2048, two-plane int8): CTA 128x128, warp 32x64, BK=64,
// 3 x s8 m16n8k32 per logical product into two s32 acc sets.
// 3-stage cp.async ring, one sync per iter. Triangle bc>=br + mirror.
// dot = di*dj*(S1 + S2/128); d2 = max(ni+nj-2dot, 0) -> g_D.
// ===========================================================================
#define ISTG 40960                // Aa 10240 | Ab 10240 | Ba 10240 | Bb 10240
#define I_AB 10240
#define I_BA 20480
#define I_BB 30720
#define ISMEM_DYN (3 * ISTG)      // 122880 B

__device__ __forceinline__ void load_stage_i(uint32_t sb, int aBase, int bBase, int kt)
{
    int tid = threadIdx.x;
    #pragma unroll
    for (int p = 0; p < 2; p++) {
        int c = tid + p * 256;
        int row = c >> 2, ch = c & 3;          // 128 rows x 4 x 16B chunks
        uint32_t d = sb + row * ROWB + ch * 16;
        size_t offA = (size_t)(aBase + row) * DF + kt + ch * 16;
        CP_ASYNC16(d,        g_fa + offA);
        CP_ASYNC16(d + I_AB, g_fb + offA);
        size_t offB = (size_t)(bBase + row) * DF + kt + ch * 16;
        CP_ASYNC16(d + I_BA, g_fa + offB);
        CP_ASYNC16(d + I_BB, g_fb + offB);
    }
}

__global__ void __launch_bounds__(256, 1) dist_gemm_kernel()
{
    const int bc = blockIdx.x, br = blockIdx.y;
    if (bc < br) return;

    extern __shared__ char smem[];
    uint32_t sb = smem_u32(smem);
    const int tid = threadIdx.x, wid = tid >> 5, lane = tid & 31;
    const int aBase = br * 128, bBase = bc * 128;
    const int warpM = (wid & 3) * 32, warpN = (wid >> 2) * 64;

    int acc1[2][8][4], acc2[2][8][4];
    #pragma unroll
    for (int m = 0; m < 2; m++)
        #pragma unroll
        for (int j = 0; j < 8; j++)
            #pragma unroll
            for (int q = 0; q < 4; q++) { acc1[m][j][q] = 0; acc2[m][j][q] = 0; }

    const int aRow = lane & 15, aChunk = (lane >> 4) & 1;
    const int bRow = (lane & 7) | ((lane & 16) >> 1);
    const int bChunk = (lane >> 3) & 1;

    load_stage_i(sb, aBase, bBase, 0);
    CP_COMMIT();
    load_stage_i(sb + ISTG, aBase, bBase, 64);
    CP_COMMIT();

    const int NK = DF / 64;
    for (int it = 0; it < NK; it++) {
        CP_WAIT1();
        __syncthreads();

        const uint32_t Ab = sb + (it % 3) * ISTG;
        const uint32_t Bb = Ab + I_BA;
        #pragma unroll
        for (int ks = 0; ks < 2; ks++) {      // two k32 steps per 64B row
            uint32_t aa[2][4], ab[2][4], ba[4][4], bb[4][4];
            uint32_t aAddr = Ab + (warpM + aRow) * ROWB + ks * 32 + aChunk * 16;
            LDSM4(aa[0], aAddr);
            LDSM4(aa[1], aAddr + 16 * ROWB);
            LDSM4(ab[0], aAddr + I_AB);
            LDSM4(ab[1], aAddr + I_AB + 16 * ROWB);
            uint32_t bAddr = Bb + (warpN + bRow) * ROWB + ks * 32 + bChunk * 16;
            #pragma unroll
            for (int nt = 0; nt < 4; nt++) {
                LDSM4(ba[nt], bAddr + nt * 16 * ROWB);
                LDSM4(bb[nt], bAddr + (I_BB - I_BA) + nt * 16 * ROWB);
            }
            #pragma unroll
            for (int mt = 0; mt < 2; mt++)
                #pragma unroll
                for (int j = 0; j < 8; j++) {
                    const int nt = j >> 1, hf = (j & 1) * 2;
                    MMAI8(acc1[mt][j], aa[mt], ba[nt][hf], ba[nt][hf + 1]);
                    MMAI8(acc2[mt][j], aa[mt], bb[nt][hf], bb[nt][hf + 1]);
                    MMAI8(acc2[mt][j], ab[mt], ba[nt][hf], ba[nt][hf + 1]);
                }
        }

        if (it + 2 < NK) {
            load_stage_i(sb + ((it + 2) % 3) * ISTG, aBase, bBase, (it + 2) * 64);
            CP_COMMIT();
        }
    }

    // ---- epilogue ----
    __shared__ float sNi[128], sNj[128], sDi[128], sDj[128];
    if (tid < 128) { sNi[tid] = g_fn[aBase + tid]; sDi[tid] = g_ds[aBase + tid]; }
    else { sNj[tid - 128] = g_fn[bBase + tid - 128]; sDj[tid - 128] = g_ds[bBase + tid - 128]; }
    __syncthreads();

    float* st = (float*)smem;   // [128][129]
    #pragma unroll
    for (int mt = 0; mt < 2; mt++) {
        const int r0 = warpM + mt * 16 + (lane >> 2);
        #pragma unroll
        for (int j = 0; j < 8; j++) {
            const int c0 = warpN + (j >> 1) * 16 + (j & 1) * 8 + 2 * (lane & 3);
            #pragma unroll
            for (int q = 0; q < 4; q++) {
                const int rr = r0 + (q >> 1) * 8;
                const int cc = c0 + (q & 1);
                float dot = (float)acc1[mt][j][q] + (float)acc2[mt][j][q] * 0.0078125f;
                st[rr * 129 + cc] = fmaxf(sNi[rr] + sNj[cc] - 2.f * sDi[rr] * sDj[cc] * dot, 0.f);
            }
        }
    }
    __syncthreads();

    for (int x = tid; x < 128 * 128; x += 256) {
        int mm = x >> 7, cc = x & 127;
        g_D[(size_t)(aBase + mm) * N2 + (bBase + cc)] = st[mm * 129 + cc];
    }
    if (bc > br) {
        for (int x = tid; x < 128 * 128; x += 256) {
            int rc = x >> 7, cm = x & 127;
            g_D[(size_t)(bBase + rc) * N2 + (aBase + cm)] = st[cm * 129 + rc];
        }
    }
}

// ---------------------------------------------------------------------------
// LID: per row, exact radix-select of rank-32 / rank-512 squared distance.
// Parallel 256-wide prefix scan replaces the serial tid0 bin scan.
// ---------------------------------------------------------------------------
__global__ void __launch_bounds__(256) select_kernel(float* __restrict__ out)
{
    int r = blockIdx.x, tid = threadIdx.x;
    __shared__ unsigned skey[N2];
    __shared__ unsigned hist[256];
    __shared__ unsigned wtot[8];
    __shared__ unsigned s_prefix;
    __shared__ int s_kk;
    __shared__ float sred[256];

    const float* drow = &g_D[(size_t)r * N2];
    for (int j = tid; j < N2; j += 256)
        skey[j] = (j == r) ? 0xFFFFFFFFu : __float_as_uint(drow[j]);
    __syncthreads();

    #pragma unroll
    for (int ksel = 0; ksel < 2; ksel++) {
        const int k = (ksel == 0) ? 32 : 512;
        if (tid == 0) { s_kk = k; s_prefix = 0u; }
        __syncthreads();
        unsigned prefix = 0u, pmask = 0u;

        for (int p = 3; p >= 0; p--) {
            hist[tid] = 0u;
            __syncthreads();
            const int sh = p * 8;
            for (int j = tid; j < N2; j += 256) {
                unsigned kv = skey[j];
                unsigned bin = 0xFFFFFFFFu;
                if ((kv & pmask) == prefix) bin = (kv >> sh) & 255u;
                unsigned mm = __match_any_sync(0xFFFFFFFFu, bin);
                if (bin != 0xFFFFFFFFu && (int)(__ffs(mm) - 1) == (int)(threadIdx.x & 31))
                    atomicAdd(&hist[bin], (unsigned)__popc(mm));
            }
            __syncthreads();
            // parallel prefix scan over 256 bins
            {
                const int kk = s_kk;
                unsigned h = hist[tid];
                unsigned v = h;
                #pragma unroll
                for (int d = 1; d < 32; d <<= 1) {
                    unsigned n = __shfl_up_sync(0xFFFFFFFFu, v, d);
                    if ((tid & 31) >= d) v += n;
                }
                if ((tid & 31) == 31) wtot[tid >> 5] = v;
                __syncthreads();
                if (tid < 8) {
                    unsigned t = wtot[tid];
                    #pragma unroll
                    for (int d = 1; d < 8; d <<= 1) {
                        unsigned n = __shfl_up_sync(0xFFu, t, d);
                        if (tid >= d) t += n;
                    }
                    wtot[tid] = t;
                }
                __syncthreads();
                unsigned incl = v + ((tid >= 32) ? wtot[(tid >> 5) - 1] : 0u);
                unsigned excl = incl - h;
                if ((unsigned)kk > excl && (unsigned)kk <= incl) {
                    s_prefix = prefix | ((unsigned)tid << sh);
                    s_kk = kk - (int)excl;
                }
            }
            __syncthreads();
            prefix = s_prefix;
            pmask |= (0xFFu << sh);
        }

        const unsigned Kk = prefix;
        const float lnK = 0.5f * logf(__uint_as_float(Kk));
        float s = 0.f;
        for (int j = tid; j < N2; j += 256) {
            unsigned kv = skey[j];
            if (kv < Kk) s += 0.5f * logf(__uint_as_float(kv)) - lnK;
        }
        sred[tid] = s; __syncthreads();
        for (int st = 128; st > 0; st >>= 1) { if (tid < st) sred[tid] += sred[tid + st]; __syncthreads(); }
        if (tid == 0)
            out[(ksel == 0 ? OUT_LIDS32 : OUT_LIDS512) + r] = -(float)k / sred[0];
        __syncthreads();
    }
}

// ---------------------------------------------------------------------------
extern "C" void kernel_launch(void* const* d_in, const int* in_sizes, int n_in,
                              void* d_out, int out_size)
{
    const float* z0 = (const float*)d_in[0];
    const float* z1 = (const float*)d_in[1];
    const float* f0 = (const float*)d_in[2];
    const float* f1 = (const float*)d_in[3];
    float* out = (float*)d_out;

    cudaFuncSetAttribute(dist_gemm_kernel,
                         cudaFuncAttributeMaxDynamicSharedMemorySize, ISMEM_DYN);
    cudaFuncSetAttribute(logits_gemm_kernel,
                         cudaFuncAttributeMaxDynamicSharedMemorySize, LSMEM_DYN);

    // order chosen so ncu's fixed capture slot (4th kernel) lands on dist_gemm
    prep_kernel<<<N2, 256>>>(z0, z1, f0, f1, out);
    logits_gemm_kernel<<<dim3(64, 64), 256, LSMEM_DYN>>>(out);
    loss_final_kernel<<<N2, 128>>>();
    dist_gemm_kernel<<<dim3(64, 64), 256, ISMEM_DYN>>>();
    finalize_kernel<<<1, 256>>>(out);
    select_kernel<<<N2, 256>>>(out);
}

// round 8
// speedup vs baseline: 1.9337x; 1.9337x over previous
#include <cuda_runtime.h>
#include <cuda_bf16.h>
#include <cstdint>

#define B4 4096
#define N2 8192
#define DZ 128
#define DF 2048
#define LCOLS 8191

// output layout (float32): loss[1], logits[8192*8191], labels[8192], lids_k32[8192], lids_k512[8192]
#define OUT_LOSS    0ull
#define OUT_LOGITS  1ull
#define OUT_LABELS  (1ull + (unsigned long long)N2 * LCOLS)
#define OUT_LIDS32  (OUT_LABELS + N2)
#define OUT_LIDS512 (OUT_LIDS32 + N2)

// scratch (device globals: allocation-free per harness rules)
__device__ __nv_bfloat16 g_fhi[(size_t)N2 * DF];
__device__ __nv_bfloat16 g_flo[(size_t)N2 * DF];
__device__ __nv_bfloat16 g_zhi[N2 * DZ];
__device__ __nv_bfloat16 g_zlo[N2 * DZ];
__device__ float g_fn[N2];
__device__ float g_D[(size_t)N2 * N2];     // 256 MiB
__device__ float g_ls[64 * N2];            // per-(tile-slot,row) exp partial sums
__device__ float g_lossper[N2];

// ---------------------------------------------------------------------------
// PTX helpers (plain sm_103-safe: mma.sync / ldmatrix / cp.async only)
// ---------------------------------------------------------------------------
__device__ __forceinline__ uint32_t smem_u32(const void* p) {
    uint32_t a;
    asm("{ .reg .u64 t; cvta.to.shared.u64 t, %1; cvt.u32.u64 %0, t; }" : "=r"(a) : "l"(p));
    return a;
}

#define CP_ASYNC16(dst, src) \
    asm volatile("cp.async.cg.shared.global [%0], [%1], 16;" :: "r"(dst), "l"(src) : "memory")
#define CP_COMMIT() asm volatile("cp.async.commit_group;" ::: "memory")
#define CP_WAIT1()  asm volatile("cp.async.wait_group 1;" ::: "memory")
#define CP_WAIT0()  asm volatile("cp.async.wait_group 0;" ::: "memory")

#define LDSM4(r, addr) \
    asm volatile("ldmatrix.sync.aligned.m8n8.x4.shared.b16 {%0,%1,%2,%3}, [%4];" \
        : "=r"((r)[0]), "=r"((r)[1]), "=r"((r)[2]), "=r"((r)[3]) : "r"(addr))

#define MMA16816(d, a, b0, b1) \
    asm volatile("mma.sync.aligned.m16n8k16.row.col.f32.bf16.bf16.f32 " \
        "{%0,%1,%2,%3}, {%4,%5,%6,%7}, {%8,%9}, {%0,%1,%2,%3};" \
        : "+f"((d)[0]), "+f"((d)[1]), "+f"((d)[2]), "+f"((d)[3]) \
        : "r"((a)[0]), "r"((a)[1]), "r"((a)[2]), "r"((a)[3]), "r"(b0), "r"(b1))

// off-diag column mapping (row gi, logical col gj) -> packed col, -1 = diag
__device__ __forceinline__ int colmap(int gi, int gj) {
    if (gi < B4) {
        if (gj >= B4) return gj - B4;
        if (gj == gi) return -1;
        return B4 + gj - (gj > gi ? 1 : 0);
    } else {
        if (gj < B4) return gj;
        if (gj == gi) return -1;
        return gj - (gj > gi ? 1 : 0);
    }
}

// ---------------------------------------------------------------------------
// prep: f squared norms + bf16 splits, z normalize + bf16 splits, labels
// ---------------------------------------------------------------------------
__global__ void __launch_bounds__(256) prep_kernel(
    const float* __restrict__ z0, const float* __restrict__ z1,
    const float* __restrict__ f0, const float* __restrict__ f1,
    float* __restrict__ out)
{
    int r = blockIdx.x;
    int tid = threadIdx.x;
    __shared__ float sred[256];

    const float* f = (r < B4) ? (f0 + (size_t)r * DF) : (f1 + (size_t)(r - B4) * DF);
    float s = 0.f;
    for (int j = tid; j < DF; j += 256) {
        float v = f[j]; s += v * v;
        __nv_bfloat16 h = __float2bfloat16(v);
        g_fhi[(size_t)r * DF + j] = h;
        g_flo[(size_t)r * DF + j] = __float2bfloat16(v - __bfloat162float(h));
    }
    sred[tid] = s; __syncthreads();
    for (int st = 128; st > 0; st >>= 1) { if (tid < st) sred[tid] += sred[tid + st]; __syncthreads(); }
    if (tid == 0) g_fn[r] = sred[0];
    __syncthreads();

    const float* z = (r < B4) ? (z0 + (size_t)r * DZ) : (z1 + (size_t)(r - B4) * DZ);
    float v = (tid < DZ) ? z[tid] : 0.f;
    sred[tid] = v * v; __syncthreads();
    for (int st = 128; st > 0; st >>= 1) { if (tid < st) sred[tid] += sred[tid + st]; __syncthreads(); }
    float inv = 1.f / fmaxf(sqrtf(sred[0]), 1e-12f);
    if (tid < DZ) {
        float zn = v * inv;
        __nv_bfloat16 h = __float2bfloat16(zn);
        g_zhi[(size_t)r * DZ + tid] = h;
        g_zlo[(size_t)r * DZ + tid] = __float2bfloat16(zn - __bfloat162float(h));
    }
    if (tid == 0) out[OUT_LABELS + r] = (float)(r & (B4 - 1));
}

// ===========================================================================
// logits GEMM (K=128, split-bf16): CTA 128x128, warp 32x64, 2-stage.
// Triangle bc>=br, mirror via stride-129 smem transpose + off-diag scatter.
// Fused softmax-denominator partials (exp once; row sums + col sums).
// Product-outer MMA ordering for accumulator-dependency-free issue.
// ===========================================================================
#define LSTAGE 40960              // Ah 10240 | Al 10240 | Bh 10240 | Bl 10240
#define ROWB 80                   // 64B data + 16B pad
#define LSMEM_DYN (2 * LSTAGE)

__device__ __forceinline__ void load_stage_l(
    uint32_t sb, const __nv_bfloat16* __restrict__ hi, const __nv_bfloat16* __restrict__ lo,
    int aBase, int bBase, int kt)
{
    int tid = threadIdx.x;
    #pragma unroll
    for (int p = 0; p < 2; p++) {
        int c = tid + p * 256;
        int row = c >> 2, ch = c & 3;
        size_t offA = (size_t)(aBase + row) * DZ + kt + ch * 8;
        size_t offB = (size_t)(bBase + row) * DZ + kt + ch * 8;
        uint32_t d = sb + row * ROWB + ch * 16;
        CP_ASYNC16(d,         hi + offA);
        CP_ASYNC16(d + 10240, lo + offA);
        CP_ASYNC16(d + 20480, hi + offB);
        CP_ASYNC16(d + 30720, lo + offB);
    }
}

__global__ void __launch_bounds__(256, 1) logits_gemm_kernel(float* __restrict__ out)
{
    const int bc = blockIdx.x, br = blockIdx.y;
    if (bc < br) return;

    extern __shared__ char smem[];
    uint32_t sb = smem_u32(smem);
    const int tid = threadIdx.x, wid = tid >> 5, lane = tid & 31;
    const int aBase = br * 128, bBase = bc * 128;
    const int warpM = (wid & 3) * 32, warpN = (wid >> 2) * 64;

    const __nv_bfloat16* hi = &g_zhi[0];
    const __nv_bfloat16* lo = &g_zlo[0];

    float acc[2][8][4];
    #pragma unroll
    for (int m = 0; m < 2; m++)
        #pragma unroll
        for (int j = 0; j < 8; j++)
            #pragma unroll
            for (int q = 0; q < 4; q++) acc[m][j][q] = 0.f;

    const int aRow = lane & 15, aChunk = (lane >> 4) & 1;
    const int bRow = (lane & 7) | ((lane & 16) >> 1);
    const int bChunk = (lane >> 3) & 1;

    load_stage_l(sb, hi, lo, aBase, bBase, 0);
    CP_COMMIT();

    const int NK = DZ / 32;
    for (int it = 0; it < NK; it++) {
        const int s = it & 1;
        if (it + 1 < NK) {
            load_stage_l(sb + (s ^ 1) * LSTAGE, hi, lo, aBase, bBase, (it + 1) * 32);
            CP_COMMIT();
            CP_WAIT1();
        } else {
            CP_WAIT0();
        }
        __syncthreads();

        const uint32_t Ab = sb + s * LSTAGE;
        const uint32_t Bb = Ab + 20480;
        #pragma unroll
        for (int ks = 0; ks < 2; ks++) {
            uint32_t ah[2][4], al[2][4], bh[4][4], bl[4][4];
            uint32_t aAddr = Ab + (warpM + aRow) * ROWB + ks * 32 + aChunk * 16;
            LDSM4(ah[0], aAddr);
            LDSM4(ah[1], aAddr + 16 * ROWB);
            LDSM4(al[0], aAddr + 10240);
            LDSM4(al[1], aAddr + 10240 + 16 * ROWB);
            uint32_t bAddr = Bb + (warpN + bRow) * ROWB + ks * 32 + bChunk * 16;
            #pragma unroll
            for (int nt = 0; nt < 4; nt++) {
                LDSM4(bh[nt], bAddr + nt * 16 * ROWB);
                LDSM4(bl[nt], bAddr + 10240 + nt * 16 * ROWB);
            }
            #pragma unroll
            for (int mt = 0; mt < 2; mt++)
                #pragma unroll
                for (int j = 0; j < 8; j++)
                    MMA16816(acc[mt][j], ah[mt], bh[j >> 1][(j & 1) * 2], bh[j >> 1][(j & 1) * 2 + 1]);
            #pragma unroll
            for (int mt = 0; mt < 2; mt++)
                #pragma unroll
                for (int j = 0; j < 8; j++)
                    MMA16816(acc[mt][j], ah[mt], bl[j >> 1][(j & 1) * 2], bl[j >> 1][(j & 1) * 2 + 1]);
            #pragma unroll
            for (int mt = 0; mt < 2; mt++)
                #pragma unroll
                for (int j = 0; j < 8; j++)
                    MMA16816(acc[mt][j], al[mt], bh[j >> 1][(j & 1) * 2], bh[j >> 1][(j & 1) * 2 + 1]);
        }
        __syncthreads();
    }

    float* st = (float*)smem;
    #pragma unroll
    for (int mt = 0; mt < 2; mt++) {
        const int r0 = warpM + mt * 16 + (lane >> 2);
        #pragma unroll
        for (int j = 0; j < 8; j++) {
            const int c0 = warpN + (j >> 1) * 16 + (j & 1) * 8 + 2 * (lane & 3);
            #pragma unroll
            for (int q = 0; q < 4; q++)
                st[(r0 + (q >> 1) * 8) * 129 + c0 + (q & 1)] = 2.f * acc[mt][j][q];
        }
    }
    __syncthreads();

    for (int x = tid; x < 128 * 128; x += 256) {
        int mm = x >> 7, cc = x & 127;
        int col = colmap(aBase + mm, bBase + cc);
        if (col >= 0) out[OUT_LOGITS + (size_t)(aBase + mm) * LCOLS + col] = st[mm * 129 + cc];
    }
    if (bc > br) {
        for (int x = tid; x < 128 * 128; x += 256) {
            int rc = x >> 7, cm = x & 127;
            int col = colmap(bBase + rc, aBase + cm);
            if (col >= 0) out[OUT_LOGITS + (size_t)(bBase + rc) * LCOLS + col] = st[cm * 129 + rc];
        }
    }
    __syncthreads();

    // ---- fused exp + row/col partial sums (symmetry: triangle tiles only) ----
    for (int x = tid; x < 128 * 128; x += 256) {
        int mm = x >> 7, cc = x & 127;
        float e = __expf(st[mm * 129 + cc]);
        if (br == bc && mm == cc) e = 0.f;     // exclude diagonal
        st[mm * 129 + cc] = e;
    }
    __syncthreads();

    {   // row sums -> slot bc, rows aBase..aBase+127 (2 threads per row)
        int row = tid >> 1, half = tid & 1;
        float s = 0.f;
        #pragma unroll 4
        for (int c2 = half * 64; c2 < half * 64 + 64; c2++) s += st[row * 129 + c2];
        s += __shfl_xor_sync(0xFFFFFFFFu, s, 1);
        if (half == 0) g_ls[(size_t)bc * N2 + aBase + row] = s;
    }
    if (bc > br) {   // col sums -> slot br, rows bBase..bBase+127
        int col = tid >> 1, half = tid & 1;
        float s = 0.f;
        #pragma unroll 4
        for (int r2 = half * 64; r2 < half * 64 + 64; r2++) s += st[r2 * 129 + col];
        s += __shfl_xor_sync(0xFFFFFFFFu, s, 1);
        if (half == 0) g_ls[(size_t)br * N2 + bBase + col] = s;
    }
}

// ---------------------------------------------------------------------------
// loss_final: per row, S = sum of 64 partials; pos = 2*dot(z0n, z1n)
// ---------------------------------------------------------------------------
__global__ void __launch_bounds__(128) loss_final_kernel()
{
    int r = blockIdx.x, tid = threadIdx.x;
    int pr = (r < B4) ? r + B4 : r - B4;

    float a = (float)g_zhi[(size_t)r * DZ + tid] + (float)g_zlo[(size_t)r * DZ + tid];
    float b = (float)g_zhi[(size_t)pr * DZ + tid] + (float)g_zlo[(size_t)pr * DZ + tid];
    float p = a * b;
    float S = (tid < 64) ? g_ls[(size_t)tid * N2 + r] : 0.f;

    #pragma unroll
    for (int d = 16; d > 0; d >>= 1) {
        p += __shfl_xor_sync(0xFFFFFFFFu, p, d);
        S += __shfl_xor_sync(0xFFFFFFFFu, S, d);
    }
    __shared__ float sp[4], sS[4];
    if ((tid & 31) == 0) { sp[tid >> 5] = p; sS[tid >> 5] = S; }
    __syncthreads();
    if (tid == 0) {
        float P = sp[0] + sp[1] + sp[2] + sp[3];
        float SS = sS[0] + sS[1] + sS[2] + sS[3];
        g_lossper[r] = logf(SS) - 2.f * P;
    }
}

__global__ void __launch_bounds__(256) finalize_kernel(float* __restrict__ out)
{
    __shared__ double sred[256];
    int tid = threadIdx.x;
    double s = 0.0;
    for (int j = tid; j < N2; j += 256) s += (double)g_lossper[j];
    sred[tid] = s; __syncthreads();
    for (int st = 128; st > 0; st >>= 1) { if (tid < st) sred[tid] += sred[tid + st]; __syncthreads(); }
    if (tid == 0) out[OUT_LOSS] = (float)(sred[0] / (double)N2);
}

// ===========================================================================
// dist GEMM (K=2048, split-bf16): CTA 256x128, warp 64x64 (8 warps), BK=64,
// 2-stage (221KB smem), ONE wait + ONE sync per iter (32 iters).
// Product-outer MMA ordering. Tiles bc >= 2*br; mirror writes gj > gi.
// d2 = max(ni+nj-2dot, 0) -> g_D.
// ===========================================================================
#define DROW 144                  // 128B data + 16B pad
#define D_AL2 36864               // A-lo offset   (256*144)
#define D_BH2 73728               // B-hi offset
#define D_BL2 92160               // B-lo offset   (+128*144)
#define DSTG2 110592              // bytes per stage
#define DSMEM_DYN (2 * DSTG2)     // 221184

__device__ __forceinline__ void load_stage_d(uint32_t sb, int aBase, int bBase, int kt)
{
    int tid = threadIdx.x;
    #pragma unroll
    for (int p = 0; p < 8; p++) {
        int c = tid + p * 256;
        int row = c >> 3, ch = c & 7;
        size_t off = (size_t)(aBase + row) * DF + kt + ch * 8;
        uint32_t d = sb + row * DROW + ch * 16;
        CP_ASYNC16(d,         g_fhi + off);
        CP_ASYNC16(d + D_AL2, g_flo + off);
    }
    #pragma unroll
    for (int p = 0; p < 4; p++) {
        int c = tid + p * 256;
        int row = c >> 3, ch = c & 7;
        size_t off = (size_t)(bBase + row) * DF + kt + ch * 8;
        uint32_t d = sb + D_BH2 + row * DROW + ch * 16;
        CP_ASYNC16(d,                   g_fhi + off);
        CP_ASYNC16(d + (D_BL2 - D_BH2), g_flo + off);
    }
}

__global__ void __launch_bounds__(256, 1) dist_gemm_kernel()
{
    const int bc = blockIdx.x, br = blockIdx.y;
    if (bc < 2 * br) return;

    extern __shared__ char smem[];
    uint32_t sb = smem_u32(smem);
    const int tid = threadIdx.x, wid = tid >> 5, lane = tid & 31;
    const int aBase = br * 256, bBase = bc * 128;
    const int warpM = (wid & 3) * 64, warpN = (wid >> 2) * 64;

    float acc[4][8][4];
    #pragma unroll
    for (int m = 0; m < 4; m++)
        #pragma unroll
        for (int j = 0; j < 8; j++)
            #pragma unroll
            for (int q = 0; q < 4; q++) acc[m][j][q] = 0.f;

    const int aRow = lane & 15, aChunk = (lane >> 4) & 1;
    const int bRow = (lane & 7) | ((lane & 16) >> 1);
    const int bChunk = (lane >> 3) & 1;

    load_stage_d(sb, aBase, bBase, 0);
    CP_COMMIT();

    const int NK = DF / 64;    // 32
    for (int it = 0; it < NK; it++) {
        CP_WAIT0();
        __syncthreads();
        if (it + 1 < NK) {
            load_stage_d(sb + ((it + 1) & 1) * DSTG2, aBase, bBase, (it + 1) * 64);
            CP_COMMIT();
        }

        const uint32_t Ab = sb + (it & 1) * DSTG2;
        const uint32_t Bb = Ab + D_BH2;
        #pragma unroll
        for (int ks = 0; ks < 4; ks++) {
            uint32_t ah[4][4], al[4][4], bh[4][4], bl[4][4];
            uint32_t aAddr = Ab + (warpM + aRow) * DROW + ks * 32 + aChunk * 16;
            #pragma unroll
            for (int mt = 0; mt < 4; mt++) {
                LDSM4(ah[mt], aAddr + mt * 16 * DROW);
                LDSM4(al[mt], aAddr + D_AL2 + mt * 16 * DROW);
            }
            uint32_t bAddr = Bb + (warpN + bRow) * DROW + ks * 32 + bChunk * 16;
            #pragma unroll
            for (int nt = 0; nt < 4; nt++) {
                LDSM4(bh[nt], bAddr + nt * 16 * DROW);
                LDSM4(bl[nt], bAddr + (D_BL2 - D_BH2) + nt * 16 * DROW);
            }
            // product-outer ordering: 32 independent MMAs between acc reuse
            #pragma unroll
            for (int mt = 0; mt < 4; mt++)
                #pragma unroll
                for (int j = 0; j < 8; j++)
                    MMA16816(acc[mt][j], ah[mt], bh[j >> 1][(j & 1) * 2], bh[j >> 1][(j & 1) * 2 + 1]);
            #pragma unroll
            for (int mt = 0; mt < 4; mt++)
                #pragma unroll
                for (int j = 0; j < 8; j++)
                    MMA16816(acc[mt][j], ah[mt], bl[j >> 1][(j & 1) * 2], bl[j >> 1][(j & 1) * 2 + 1]);
            #pragma unroll
            for (int mt = 0; mt < 4; mt++)
                #pragma unroll
                for (int j = 0; j < 8; j++)
                    MMA16816(acc[mt][j], al[mt], bh[j >> 1][(j & 1) * 2], bh[j >> 1][(j & 1) * 2 + 1]);
        }
    }

    // ---- epilogue ----
    __shared__ float sNi[256], sNj[128];
    sNi[tid] = g_fn[aBase + tid];
    if (tid < 128) sNj[tid] = g_fn[bBase + tid];
    __syncthreads();

    float* st = (float*)smem;   // [256][129]
    #pragma unroll
    for (int mt = 0; mt < 4; mt++) {
        const int r0 = warpM + mt * 16 + (lane >> 2);
        #pragma unroll
        for (int j = 0; j < 8; j++) {
            const int c0 = warpN + (j >> 1) * 16 + (j & 1) * 8 + 2 * (lane & 3);
            #pragma unroll
            for (int q = 0; q < 4; q++) {
                const int rr = r0 + (q >> 1) * 8;
                const int cc = c0 + (q & 1);
                st[rr * 129 + cc] = fmaxf(sNi[rr] + sNj[cc] - 2.f * acc[mt][j][q], 0.f);
            }
        }
    }
    __syncthreads();

    for (int x = tid; x < 256 * 128; x += 256) {
        int mm = x >> 7, cc = x & 127;
        g_D[(size_t)(aBase + mm) * N2 + (bBase + cc)] = st[mm * 129 + cc];
    }
    for (int x = tid; x < 128 * 256; x += 256) {
        int rc = x >> 8, cm = x & 255;
        int gi = aBase + cm, gj = bBase + rc;
        if (gj > gi) g_D[(size_t)gj * N2 + gi] = st[cm * 129 + rc];
    }
}

// ---------------------------------------------------------------------------
// LID: per row, exact radix-select of rank-32 / rank-512 squared distance.
// Parallel 256-wide prefix scan over histogram bins.
// ---------------------------------------------------------------------------
__global__ void __launch_bounds__(256) select_kernel(float* __restrict__ out)
{
    int r = blockIdx.x, tid = threadIdx.x;
    __shared__ unsigned skey[N2];
    __shared__ unsigned hist[256];
    __shared__ unsigned wtot[8];
    __shared__ unsigned s_prefix;
    __shared__ int s_kk;
    __shared__ float sred[256];

    const float* drow = &g_D[(size_t)r * N2];
    for (int j = tid; j < N2; j += 256)
        skey[j] = (j == r) ? 0xFFFFFFFFu : __float_as_uint(drow[j]);
    __syncthreads();

    #pragma unroll
    for (int ksel = 0; ksel < 2; ksel++) {
        const int k = (ksel == 0) ? 32 : 512;
        if (tid == 0) { s_kk = k; s_prefix = 0u; }
        __syncthreads();
        unsigned prefix = 0u, pmask = 0u;

        for (int p = 3; p >= 0; p--) {
            hist[tid] = 0u;
            __syncthreads();
            const int sh = p * 8;
            for (int j = tid; j < N2; j += 256) {
                unsigned kv = skey[j];
                unsigned bin = 0xFFFFFFFFu;
                if ((kv & pmask) == prefix) bin = (kv >> sh) & 255u;
                unsigned mm = __match_any_sync(0xFFFFFFFFu, bin);
                if (bin != 0xFFFFFFFFu && (int)(__ffs(mm) - 1) == (int)(threadIdx.x & 31))
                    atomicAdd(&hist[bin], (unsigned)__popc(mm));
            }
            __syncthreads();
            {
                const int kk = s_kk;
                unsigned h = hist[tid];
                unsigned v = h;
                #pragma unroll
                for (int d = 1; d < 32; d <<= 1) {
                    unsigned n = __shfl_up_sync(0xFFFFFFFFu, v, d);
                    if ((tid & 31) >= d) v += n;
                }
                if ((tid & 31) == 31) wtot[tid >> 5] = v;
                __syncthreads();
                if (tid < 8) {
                    unsigned t = wtot[tid];
                    #pragma unroll
                    for (int d = 1; d < 8; d <<= 1) {
                        unsigned n = __shfl_up_sync(0xFFu, t, d);
                        if (tid >= d) t += n;
                    }
                    wtot[tid] = t;
                }
                __syncthreads();
                unsigned incl = v + ((tid >= 32) ? wtot[(tid >> 5) - 1] : 0u);
                unsigned excl = incl - h;
                if ((unsigned)kk > excl && (unsigned)kk <= incl) {
                    s_prefix = prefix | ((unsigned)tid << sh);
                    s_kk = kk - (int)excl;
                }
            }
            __syncthreads();
            prefix = s_prefix;
            pmask |= (0xFFu << sh);
        }

        const unsigned Kk = prefix;
        const float lnK = 0.5f * logf(__uint_as_float(Kk));
        float s = 0.f;
        for (int j = tid; j < N2; j += 256) {
            unsigned kv = skey[j];
            if (kv < Kk) s += 0.5f * logf(__uint_as_float(kv)) - lnK;
        }
        sred[tid] = s; __syncthreads();
        for (int st = 128; st > 0; st >>= 1) { if (tid < st) sred[tid] += sred[tid + st]; __syncthreads(); }
        if (tid == 0)
            out[(ksel == 0 ? OUT_LIDS32 : OUT_LIDS512) + r] = -(float)k / sred[0];
        __syncthreads();
    }
}

// ---------------------------------------------------------------------------
extern "C" void kernel_launch(void* const* d_in, const int* in_sizes, int n_in,
                              void* d_out, int out_size)
{
    const float* z0 = (const float*)d_in[0];
    const float* z1 = (const float*)d_in[1];
    const float* f0 = (const float*)d_in[2];
    const float* f1 = (const float*)d_in[3];
    float* out = (float*)d_out;

    cudaFuncSetAttribute(dist_gemm_kernel,
                         cudaFuncAttributeMaxDynamicSharedMemorySize, DSMEM_DYN);
    cudaFuncSetAttribute(logits_gemm_kernel,
                         cudaFuncAttributeMaxDynamicSharedMemorySize, LSMEM_DYN);

    // order chosen so ncu's fixed capture slot (4th kernel) lands on dist_gemm
    prep_kernel<<<N2, 256>>>(z0, z1, f0, f1, out);
    logits_gemm_kernel<<<dim3(64, 64), 256, LSMEM_DYN>>>(out);
    loss_final_kernel<<<N2, 128>>>();
    dist_gemm_kernel<<<dim3(64, 32), 256, DSMEM_DYN>>>();
    finalize_kernel<<<1, 256>>>(out);
    select_kernel<<<N2, 256>>>(out);
}

// round 9
// speedup vs baseline: 2.0698x; 1.0704x over previous
#include <cuda_runtime.h>
#include <cuda_bf16.h>
#include <cstdint>

#define B4 4096
#define N2 8192
#define DZ 128
#define DF 2048
#define LCOLS 8191

// output layout (float32): loss[1], logits[8192*8191], labels[8192], lids_k32[8192], lids_k512[8192]
#define OUT_LOSS    0ull
#define OUT_LOGITS  1ull
#define OUT_LABELS  (1ull + (unsigned long long)N2 * LCOLS)
#define OUT_LIDS32  (OUT_LABELS + N2)
#define OUT_LIDS512 (OUT_LIDS32 + N2)

// scratch (device globals: allocation-free per harness rules)
__device__ __nv_bfloat16 g_fhi[(size_t)N2 * DF];
__device__ __nv_bfloat16 g_flo[(size_t)N2 * DF];
__device__ __nv_bfloat16 g_zhi[N2 * DZ];
__device__ __nv_bfloat16 g_zlo[N2 * DZ];
__device__ float g_fn[N2];
__device__ float g_D[(size_t)N2 * N2];     // 256 MiB
__device__ float g_ls[64 * N2];            // per-(tile-slot,row) exp partial sums
__device__ float g_lossper[N2];

// ---------------------------------------------------------------------------
// PTX helpers (plain sm_103-safe: mma.sync / ldmatrix / cp.async only)
// ---------------------------------------------------------------------------
__device__ __forceinline__ uint32_t smem_u32(const void* p) {
    uint32_t a;
    asm("{ .reg .u64 t; cvta.to.shared.u64 t, %1; cvt.u32.u64 %0, t; }" : "=r"(a) : "l"(p));
    return a;
}

#define CP_ASYNC16(dst, src) \
    asm volatile("cp.async.cg.shared.global [%0], [%1], 16;" :: "r"(dst), "l"(src) : "memory")
#define CP_COMMIT() asm volatile("cp.async.commit_group;" ::: "memory")
#define CP_WAIT1()  asm volatile("cp.async.wait_group 1;" ::: "memory")
#define CP_WAIT0()  asm volatile("cp.async.wait_group 0;" ::: "memory")

#define LDSM4(r, addr) \
    asm volatile("ldmatrix.sync.aligned.m8n8.x4.shared.b16 {%0,%1,%2,%3}, [%4];" \
        : "=r"((r)[0]), "=r"((r)[1]), "=r"((r)[2]), "=r"((r)[3]) : "r"(addr))

#define MMA16816(d, a, b0, b1) \
    asm volatile("mma.sync.aligned.m16n8k16.row.col.f32.bf16.bf16.f32 " \
        "{%0,%1,%2,%3}, {%4,%5,%6,%7}, {%8,%9}, {%0,%1,%2,%3};" \
        : "+f"((d)[0]), "+f"((d)[1]), "+f"((d)[2]), "+f"((d)[3]) \
        : "r"((a)[0]), "r"((a)[1]), "r"((a)[2]), "r"((a)[3]), "r"(b0), "r"(b1))

// off-diag column mapping (row gi, logical col gj) -> packed col, -1 = diag
__device__ __forceinline__ int colmap(int gi, int gj) {
    if (gi < B4) {
        if (gj >= B4) return gj - B4;
        if (gj == gi) return -1;
        return B4 + gj - (gj > gi ? 1 : 0);
    } else {
        if (gj < B4) return gj;
        if (gj == gi) return -1;
        return gj - (gj > gi ? 1 : 0);
    }
}

// ---------------------------------------------------------------------------
// prep: f squared norms + bf16 splits, z normalize + bf16 splits, labels
// ---------------------------------------------------------------------------
__global__ void __launch_bounds__(256) prep_kernel(
    const float* __restrict__ z0, const float* __restrict__ z1,
    const float* __restrict__ f0, const float* __restrict__ f1,
    float* __restrict__ out)
{
    int r = blockIdx.x;
    int tid = threadIdx.x;
    __shared__ float sred[256];

    const float* f = (r < B4) ? (f0 + (size_t)r * DF) : (f1 + (size_t)(r - B4) * DF);
    float s = 0.f;
    for (int j = tid; j < DF; j += 256) {
        float v = f[j]; s += v * v;
        __nv_bfloat16 h = __float2bfloat16(v);
        g_fhi[(size_t)r * DF + j] = h;
        g_flo[(size_t)r * DF + j] = __float2bfloat16(v - __bfloat162float(h));
    }
    sred[tid] = s; __syncthreads();
    for (int st = 128; st > 0; st >>= 1) { if (tid < st) sred[tid] += sred[tid + st]; __syncthreads(); }
    if (tid == 0) g_fn[r] = sred[0];
    __syncthreads();

    const float* z = (r < B4) ? (z0 + (size_t)r * DZ) : (z1 + (size_t)(r - B4) * DZ);
    float v = (tid < DZ) ? z[tid] : 0.f;
    sred[tid] = v * v; __syncthreads();
    for (int st = 128; st > 0; st >>= 1) { if (tid < st) sred[tid] += sred[tid + st]; __syncthreads(); }
    float inv = 1.f / fmaxf(sqrtf(sred[0]), 1e-12f);
    if (tid < DZ) {
        float zn = v * inv;
        __nv_bfloat16 h = __float2bfloat16(zn);
        g_zhi[(size_t)r * DZ + tid] = h;
        g_zlo[(size_t)r * DZ + tid] = __float2bfloat16(zn - __bfloat162float(h));
    }
    if (tid == 0) out[OUT_LABELS + r] = (float)(r & (B4 - 1));
}

// ===========================================================================
// shared GEMM building blocks: CTA 128x128, warp 32x64, BK=32, 2-stage,
// 2 CTAs/SM co-residency. ROWB=80 (64B data + 16B pad).
// ===========================================================================
#define GSTG 40960                // Ah 10240 | Al 10240 | Bh 10240 | Bl 10240
#define G_AL 10240
#define G_BH 20480
#define G_BL 30720
#define ROWB 80
#define GSMEM_DYN (2 * GSTG)      // 81920 -> 2 CTAs/SM

template<int KD>
__device__ __forceinline__ void load_stage_g(
    uint32_t sb, const __nv_bfloat16* __restrict__ hi, const __nv_bfloat16* __restrict__ lo,
    int aBase, int bBase, int kt)
{
    int tid = threadIdx.x;
    #pragma unroll
    for (int p = 0; p < 2; p++) {
        int c = tid + p * 256;
        int row = c >> 2, ch = c & 3;
        size_t offA = (size_t)(aBase + row) * KD + kt + ch * 8;
        size_t offB = (size_t)(bBase + row) * KD + kt + ch * 8;
        uint32_t d = sb + row * ROWB + ch * 16;
        CP_ASYNC16(d,        hi + offA);
        CP_ASYNC16(d + G_AL, lo + offA);
        CP_ASYNC16(d + G_BH, hi + offB);
        CP_ASYNC16(d + G_BL, lo + offB);
    }
}

// mainloop macro body shared by both GEMMs (acc[2][8][4], warp 32x64)
template<int KD>
__device__ __forceinline__ void gemm_mainloop(
    uint32_t sb, const __nv_bfloat16* hi, const __nv_bfloat16* lo,
    int aBase, int bBase, float acc[2][8][4])
{
    const int tid = threadIdx.x, wid = tid >> 5, lane = tid & 31;
    const int warpM = (wid & 3) * 32, warpN = (wid >> 2) * 64;
    const int aRow = lane & 15, aChunk = (lane >> 4) & 1;
    const int bRow = (lane & 7) | ((lane & 16) >> 1);
    const int bChunk = (lane >> 3) & 1;

    load_stage_g<KD>(sb, hi, lo, aBase, bBase, 0);
    CP_COMMIT();

    const int NK = KD / 32;
    for (int it = 0; it < NK; it++) {
        const int s = it & 1;
        if (it + 1 < NK) {
            load_stage_g<KD>(sb + (s ^ 1) * GSTG, hi, lo, aBase, bBase, (it + 1) * 32);
            CP_COMMIT();
            CP_WAIT1();
        } else {
            CP_WAIT0();
        }
        __syncthreads();

        const uint32_t Ab = sb + s * GSTG;
        const uint32_t Bb = Ab + G_BH;
        #pragma unroll
        for (int ks = 0; ks < 2; ks++) {
            uint32_t ah[2][4], al[2][4], bh[4][4], bl[4][4];
            uint32_t aAddr = Ab + (warpM + aRow) * ROWB + ks * 32 + aChunk * 16;
            LDSM4(ah[0], aAddr);
            LDSM4(ah[1], aAddr + 16 * ROWB);
            LDSM4(al[0], aAddr + G_AL);
            LDSM4(al[1], aAddr + G_AL + 16 * ROWB);
            uint32_t bAddr = Bb + (warpN + bRow) * ROWB + ks * 32 + bChunk * 16;
            #pragma unroll
            for (int nt = 0; nt < 4; nt++) {
                LDSM4(bh[nt], bAddr + nt * 16 * ROWB);
                LDSM4(bl[nt], bAddr + (G_BL - G_BH) + nt * 16 * ROWB);
            }
            #pragma unroll
            for (int mt = 0; mt < 2; mt++)
                #pragma unroll
                for (int j = 0; j < 8; j++)
                    MMA16816(acc[mt][j], ah[mt], bh[j >> 1][(j & 1) * 2], bh[j >> 1][(j & 1) * 2 + 1]);
            #pragma unroll
            for (int mt = 0; mt < 2; mt++)
                #pragma unroll
                for (int j = 0; j < 8; j++)
                    MMA16816(acc[mt][j], ah[mt], bl[j >> 1][(j & 1) * 2], bl[j >> 1][(j & 1) * 2 + 1]);
            #pragma unroll
            for (int mt = 0; mt < 2; mt++)
                #pragma unroll
                for (int j = 0; j < 8; j++)
                    MMA16816(acc[mt][j], al[mt], bh[j >> 1][(j & 1) * 2], bh[j >> 1][(j & 1) * 2 + 1]);
        }
        __syncthreads();
    }
}

// ===========================================================================
// logits GEMM (K=128): triangle bc>=br, mirror via stride-129 transpose,
// off-diag scatter + fused exp/row/col softmax partials.
// ===========================================================================
__global__ void __launch_bounds__(256, 2) logits_gemm_kernel(float* __restrict__ out)
{
    const int bc = blockIdx.x, br = blockIdx.y;
    if (bc < br) return;

    extern __shared__ char smem[];
    uint32_t sb = smem_u32(smem);
    const int tid = threadIdx.x, wid = tid >> 5, lane = tid & 31;
    const int aBase = br * 128, bBase = bc * 128;
    const int warpM = (wid & 3) * 32, warpN = (wid >> 2) * 64;

    float acc[2][8][4];
    #pragma unroll
    for (int m = 0; m < 2; m++)
        #pragma unroll
        for (int j = 0; j < 8; j++)
            #pragma unroll
            for (int q = 0; q < 4; q++) acc[m][j][q] = 0.f;

    gemm_mainloop<DZ>(sb, &g_zhi[0], &g_zlo[0], aBase, bBase, acc);

    float* st = (float*)smem;
    #pragma unroll
    for (int mt = 0; mt < 2; mt++) {
        const int r0 = warpM + mt * 16 + (lane >> 2);
        #pragma unroll
        for (int j = 0; j < 8; j++) {
            const int c0 = warpN + (j >> 1) * 16 + (j & 1) * 8 + 2 * (lane & 3);
            #pragma unroll
            for (int q = 0; q < 4; q++)
                st[(r0 + (q >> 1) * 8) * 129 + c0 + (q & 1)] = 2.f * acc[mt][j][q];
        }
    }
    __syncthreads();

    for (int x = tid; x < 128 * 128; x += 256) {
        int mm = x >> 7, cc = x & 127;
        int col = colmap(aBase + mm, bBase + cc);
        if (col >= 0) out[OUT_LOGITS + (size_t)(aBase + mm) * LCOLS + col] = st[mm * 129 + cc];
    }
    if (bc > br) {
        for (int x = tid; x < 128 * 128; x += 256) {
            int rc = x >> 7, cm = x & 127;
            int col = colmap(bBase + rc, aBase + cm);
            if (col >= 0) out[OUT_LOGITS + (size_t)(bBase + rc) * LCOLS + col] = st[cm * 129 + rc];
        }
    }
    __syncthreads();

    // ---- fused exp + row/col partial sums (symmetry: triangle tiles only) ----
    for (int x = tid; x < 128 * 128; x += 256) {
        int mm = x >> 7, cc = x & 127;
        float e = __expf(st[mm * 129 + cc]);
        if (br == bc && mm == cc) e = 0.f;     // exclude diagonal
        st[mm * 129 + cc] = e;
    }
    __syncthreads();

    {   // row sums -> slot bc, rows aBase..aBase+127 (2 threads per row)
        int row = tid >> 1, half = tid & 1;
        float s = 0.f;
        #pragma unroll 4
        for (int c2 = half * 64; c2 < half * 64 + 64; c2++) s += st[row * 129 + c2];
        s += __shfl_xor_sync(0xFFFFFFFFu, s, 1);
        if (half == 0) g_ls[(size_t)bc * N2 + aBase + row] = s;
    }
    if (bc > br) {   // col sums -> slot br, rows bBase..bBase+127
        int col = tid >> 1, half = tid & 1;
        float s = 0.f;
        #pragma unroll 4
        for (int r2 = half * 64; r2 < half * 64 + 64; r2++) s += st[r2 * 129 + col];
        s += __shfl_xor_sync(0xFFFFFFFFu, s, 1);
        if (half == 0) g_ls[(size_t)br * N2 + bBase + col] = s;
    }
}

// ===========================================================================
// dist GEMM (K=2048): triangle bc>=br, 2080 tiles, 2 CTAs/SM.
// d2 = max(ni+nj-2dot, 0) -> g_D (+mirror for bc>br).
// ===========================================================================
__global__ void __launch_bounds__(256, 2) dist_gemm_kernel()
{
    const int bc = blockIdx.x, br = blockIdx.y;
    if (bc < br) return;

    extern __shared__ char smem[];
    uint32_t sb = smem_u32(smem);
    const int tid = threadIdx.x, wid = tid >> 5, lane = tid & 31;
    const int aBase = br * 128, bBase = bc * 128;
    const int warpM = (wid & 3) * 32, warpN = (wid >> 2) * 64;

    float acc[2][8][4];
    #pragma unroll
    for (int m = 0; m < 2; m++)
        #pragma unroll
        for (int j = 0; j < 8; j++)
            #pragma unroll
            for (int q = 0; q < 4; q++) acc[m][j][q] = 0.f;

    gemm_mainloop<DF>(sb, &g_fhi[0], &g_flo[0], aBase, bBase, acc);

    __shared__ float sNi[128], sNj[128];
    if (tid < 128) sNi[tid] = g_fn[aBase + tid];
    else           sNj[tid - 128] = g_fn[bBase + tid - 128];
    __syncthreads();

    float* st = (float*)smem;   // [128][129]
    #pragma unroll
    for (int mt = 0; mt < 2; mt++) {
        const int r0 = warpM + mt * 16 + (lane >> 2);
        #pragma unroll
        for (int j = 0; j < 8; j++) {
            const int c0 = warpN + (j >> 1) * 16 + (j & 1) * 8 + 2 * (lane & 3);
            #pragma unroll
            for (int q = 0; q < 4; q++) {
                const int rr = r0 + (q >> 1) * 8;
                const int cc = c0 + (q & 1);
                st[rr * 129 + cc] = fmaxf(sNi[rr] + sNj[cc] - 2.f * acc[mt][j][q], 0.f);
            }
        }
    }
    __syncthreads();

    for (int x = tid; x < 128 * 128; x += 256) {
        int mm = x >> 7, cc = x & 127;
        g_D[(size_t)(aBase + mm) * N2 + (bBase + cc)] = st[mm * 129 + cc];
    }
    if (bc > br) {
        for (int x = tid; x < 128 * 128; x += 256) {
            int rc = x >> 7, cm = x & 127;
            g_D[(size_t)(bBase + rc) * N2 + (aBase + cm)] = st[cm * 129 + rc];
        }
    }
}

// ---------------------------------------------------------------------------
// loss_final: per row, S = sum of 64 partials; pos = 2*dot(z0n, z1n)
// ---------------------------------------------------------------------------
__global__ void __launch_bounds__(128) loss_final_kernel()
{
    int r = blockIdx.x, tid = threadIdx.x;
    int pr = (r < B4) ? r + B4 : r - B4;

    float a = (float)g_zhi[(size_t)r * DZ + tid] + (float)g_zlo[(size_t)r * DZ + tid];
    float b = (float)g_zhi[(size_t)pr * DZ + tid] + (float)g_zlo[(size_t)pr * DZ + tid];
    float p = a * b;
    float S = (tid < 64) ? g_ls[(size_t)tid * N2 + r] : 0.f;

    #pragma unroll
    for (int d = 16; d > 0; d >>= 1) {
        p += __shfl_xor_sync(0xFFFFFFFFu, p, d);
        S += __shfl_xor_sync(0xFFFFFFFFu, S, d);
    }
    __shared__ float sp[4], sS[4];
    if ((tid & 31) == 0) { sp[tid >> 5] = p; sS[tid >> 5] = S; }
    __syncthreads();
    if (tid == 0) {
        float P = sp[0] + sp[1] + sp[2] + sp[3];
        float SS = sS[0] + sS[1] + sS[2] + sS[3];
        g_lossper[r] = logf(SS) - 2.f * P;
    }
}

__global__ void __launch_bounds__(256) finalize_kernel(float* __restrict__ out)
{
    __shared__ double sred[256];
    int tid = threadIdx.x;
    double s = 0.0;
    for (int j = tid; j < N2; j += 256) s += (double)g_lossper[j];
    sred[tid] = s; __syncthreads();
    for (int st = 128; st > 0; st >>= 1) { if (tid < st) sred[tid] += sred[tid + st]; __syncthreads(); }
    if (tid == 0) out[OUT_LOSS] = (float)(sred[0] / (double)N2);
}

// ---------------------------------------------------------------------------
// LID: per row, exact radix-select (12/12/8-bit passes) of rank-32 / rank-512
// squared distance (self excluded), then LID sums.
// ---------------------------------------------------------------------------
__global__ void __launch_bounds__(256) select_kernel(float* __restrict__ out)
{
    int r = blockIdx.x, tid = threadIdx.x;
    __shared__ unsigned skey[N2];      // 32 KB
    __shared__ unsigned hist[4096];    // 16 KB
    __shared__ unsigned wtot[8];
    __shared__ unsigned s_bin;
    __shared__ int s_kk;
    __shared__ float sred[256];

    const float* drow = &g_D[(size_t)r * N2];
    for (int j = tid; j < N2; j += 256)
        skey[j] = (j == r) ? 0xFFFFFFFFu : __float_as_uint(drow[j]);
    __syncthreads();

    #pragma unroll
    for (int ksel = 0; ksel < 2; ksel++) {
        const int k = (ksel == 0) ? 32 : 512;
        int kk = k;
        unsigned prefixval = 0u;       // key >> pshift == prefixval
        int pshift = 32;

        #pragma unroll
        for (int pass = 0; pass < 3; pass++) {
            const int sh = (pass == 0) ? 20 : (pass == 1) ? 8 : 0;
            const unsigned bmask = (pass < 2) ? 4095u : 255u;

            #pragma unroll
            for (int b = 0; b < 16; b++) hist[tid + b * 256] = 0u;
            __syncthreads();

            for (int j = tid; j < N2; j += 256) {
                unsigned kv = skey[j];
                bool ok = (pshift >= 32) ? true : ((kv >> pshift) == prefixval);
                if (ok) atomicAdd(&hist[(kv >> sh) & bmask], 1u);
            }
            __syncthreads();

            // block scan: each thread owns 16 consecutive bins
            {
                unsigned tsum = 0;
                #pragma unroll
                for (int b = 0; b < 16; b++) tsum += hist[tid * 16 + b];
                unsigned v = tsum;
                #pragma unroll
                for (int d = 1; d < 32; d <<= 1) {
                    unsigned n = __shfl_up_sync(0xFFFFFFFFu, v, d);
                    if ((tid & 31) >= d) v += n;
                }
                if ((tid & 31) == 31) wtot[tid >> 5] = v;
                __syncthreads();
                if (tid < 8) {
                    unsigned t = wtot[tid];
                    #pragma unroll
                    for (int d = 1; d < 8; d <<= 1) {
                        unsigned n = __shfl_up_sync(0xFFu, t, d);
                        if (tid >= d) t += n;
                    }
                    wtot[tid] = t;
                }
                __syncthreads();
                unsigned incl = v + ((tid >= 32) ? wtot[(tid >> 5) - 1] : 0u);
                unsigned excl = incl - tsum;
                if ((unsigned)kk > excl && (unsigned)kk <= incl) {
                    // target bin inside this thread's 16-bin range
                    unsigned cum = excl;
                    #pragma unroll
                    for (int b = 0; b < 16; b++) {
                        unsigned c = hist[tid * 16 + b];
                        if ((unsigned)kk <= cum + c) { s_bin = tid * 16 + b; s_kk = kk - (int)cum; break; }
                        cum += c;
                    }
                }
            }
            __syncthreads();
            prefixval = (prefixval << ((pass < 2) ? 12 : 8)) | s_bin;
            kk = s_kk;
            pshift = sh;
            __syncthreads();
        }

        const unsigned Kk = prefixval;               // exact k-th smallest key
        const float lnK = 0.5f * logf(__uint_as_float(Kk));
        float s = 0.f;
        for (int j = tid; j < N2; j += 256) {
            unsigned kv = skey[j];
            if (kv < Kk) s += 0.5f * logf(__uint_as_float(kv)) - lnK;
        }
        sred[tid] = s; __syncthreads();
        for (int st = 128; st > 0; st >>= 1) { if (tid < st) sred[tid] += sred[tid + st]; __syncthreads(); }
        if (tid == 0)
            out[(ksel == 0 ? OUT_LIDS32 : OUT_LIDS512) + r] = -(float)k / sred[0];
        __syncthreads();
    }
}

// ---------------------------------------------------------------------------
extern "C" void kernel_launch(void* const* d_in, const int* in_sizes, int n_in,
                              void* d_out, int out_size)
{
    const float* z0 = (const float*)d_in[0];
    const float* z1 = (const float*)d_in[1];
    const float* f0 = (const float*)d_in[2];
    const float* f1 = (const float*)d_in[3];
    float* out = (float*)d_out;

    cudaFuncSetAttribute(dist_gemm_kernel,
                         cudaFuncAttributeMaxDynamicSharedMemorySize, GSMEM_DYN);
    cudaFuncSetAttribute(logits_gemm_kernel,
                         cudaFuncAttributeMaxDynamicSharedMemorySize, GSMEM_DYN);

    // order chosen so ncu's fixed capture slot (4th kernel) lands on dist_gemm
    prep_kernel<<<N2, 256>>>(z0, z1, f0, f1, out);
    logits_gemm_kernel<<<dim3(64, 64), 256, GSMEM_DYN>>>(out);
    loss_final_kernel<<<N2, 128>>>();
    dist_gemm_kernel<<<dim3(64, 64), 256, GSMEM_DYN>>>();
    finalize_kernel<<<1, 256>>>(out);
    select_kernel<<<N2, 256>>>(out);
}

// round 10
// speedup vs baseline: 2.3009x; 1.1116x over previous
#include <cuda_runtime.h>
#include <cuda_bf16.h>
#include <cstdint>

#define B4 4096
#define N2 8192
#define DZ 128
#define DF 2048
#define LCOLS 8191
#define NTILE 2080                 // 64*65/2 triangle tiles

// output layout (float32): loss[1], logits[8192*8191], labels[8192], lids_k32[8192], lids_k512[8192]
#define OUT_LOSS    0ull
#define OUT_LOGITS  1ull
#define OUT_LABELS  (1ull + (unsigned long long)N2 * LCOLS)
#define OUT_LIDS32  (OUT_LABELS + N2)
#define OUT_LIDS512 (OUT_LIDS32 + N2)

// scratch (device globals: allocation-free per harness rules)
__device__ __nv_bfloat16 g_fhi[(size_t)N2 * DF];
__device__ __nv_bfloat16 g_flo[(size_t)N2 * DF];
__device__ __nv_bfloat16 g_zhi[N2 * DZ];
__device__ __nv_bfloat16 g_zlo[N2 * DZ];
__device__ float g_fn[N2];
__device__ float g_D[(size_t)N2 * N2];     // 256 MiB
__device__ float g_ls[64 * N2];            // per-(tile-slot,row) exp partial sums
__device__ float g_lossper[N2];

// ---------------------------------------------------------------------------
// PTX helpers (plain sm_103-safe: mma.sync / ldmatrix / cp.async only)
// ---------------------------------------------------------------------------
__device__ __forceinline__ uint32_t smem_u32(const void* p) {
    uint32_t a;
    asm("{ .reg .u64 t; cvta.to.shared.u64 t, %1; cvt.u32.u64 %0, t; }" : "=r"(a) : "l"(p));
    return a;
}

#define CP_ASYNC16(dst, src) \
    asm volatile("cp.async.cg.shared.global [%0], [%1], 16;" :: "r"(dst), "l"(src) : "memory")
#define CP_COMMIT() asm volatile("cp.async.commit_group;" ::: "memory")
#define CP_WAIT1()  asm volatile("cp.async.wait_group 1;" ::: "memory")
#define CP_WAIT0()  asm volatile("cp.async.wait_group 0;" ::: "memory")

#define LDSM4(r, addr) \
    asm volatile("ldmatrix.sync.aligned.m8n8.x4.shared.b16 {%0,%1,%2,%3}, [%4];" \
        : "=r"((r)[0]), "=r"((r)[1]), "=r"((r)[2]), "=r"((r)[3]) : "r"(addr))

#define MMA16816(d, a, b0, b1) \
    asm volatile("mma.sync.aligned.m16n8k16.row.col.f32.bf16.bf16.f32 " \
        "{%0,%1,%2,%3}, {%4,%5,%6,%7}, {%8,%9}, {%0,%1,%2,%3};" \
        : "+f"((d)[0]), "+f"((d)[1]), "+f"((d)[2]), "+f"((d)[3]) \
        : "r"((a)[0]), "r"((a)[1]), "r"((a)[2]), "r"((a)[3]), "r"(b0), "r"(b1))

// off-diag column mapping (row gi, logical col gj) -> packed col, -1 = diag
__device__ __forceinline__ int colmap(int gi, int gj) {
    if (gi < B4) {
        if (gj >= B4) return gj - B4;
        if (gj == gi) return -1;
        return B4 + gj - (gj > gi ? 1 : 0);
    } else {
        if (gj < B4) return gj;
        if (gj == gi) return -1;
        return gj - (gj > gi ? 1 : 0);
    }
}

// linear tile id -> (br, bc) with 0 <= br <= bc < 64
__device__ __forceinline__ void tri_decode(int t, int& br, int& bc) {
    int row = 0, rem = t;
    #pragma unroll 1
    while (rem >= 64 - row) { rem -= 64 - row; row++; }
    br = row; bc = row + rem;
}

// ---------------------------------------------------------------------------
// prep: f squared norms + bf16 splits, z normalize + bf16 splits, labels
// ---------------------------------------------------------------------------
__global__ void __launch_bounds__(256) prep_kernel(
    const float* __restrict__ z0, const float* __restrict__ z1,
    const float* __restrict__ f0, const float* __restrict__ f1,
    float* __restrict__ out)
{
    int r = blockIdx.x;
    int tid = threadIdx.x;
    __shared__ float sred[256];

    const float* f = (r < B4) ? (f0 + (size_t)r * DF) : (f1 + (size_t)(r - B4) * DF);
    float s = 0.f;
    for (int j = tid; j < DF; j += 256) {
        float v = f[j]; s += v * v;
        __nv_bfloat16 h = __float2bfloat16(v);
        g_fhi[(size_t)r * DF + j] = h;
        g_flo[(size_t)r * DF + j] = __float2bfloat16(v - __bfloat162float(h));
    }
    sred[tid] = s; __syncthreads();
    for (int st = 128; st > 0; st >>= 1) { if (tid < st) sred[tid] += sred[tid + st]; __syncthreads(); }
    if (tid == 0) g_fn[r] = sred[0];
    __syncthreads();

    const float* z = (r < B4) ? (z0 + (size_t)r * DZ) : (z1 + (size_t)(r - B4) * DZ);
    float v = (tid < DZ) ? z[tid] : 0.f;
    sred[tid] = v * v; __syncthreads();
    for (int st = 128; st > 0; st >>= 1) { if (tid < st) sred[tid] += sred[tid + st]; __syncthreads(); }
    float inv = 1.f / fmaxf(sqrtf(sred[0]), 1e-12f);
    if (tid < DZ) {
        float zn = v * inv;
        __nv_bfloat16 h = __float2bfloat16(zn);
        g_zhi[(size_t)r * DZ + tid] = h;
        g_zlo[(size_t)r * DZ + tid] = __float2bfloat16(zn - __bfloat162float(h));
    }
    if (tid == 0) out[OUT_LABELS + r] = (float)(r & (B4 - 1));
}

// ===========================================================================
// shared GEMM building blocks: CTA 128x128, warp 32x64, BK=32, 2-stage,
// 2 CTAs/SM co-residency. ROWB=80 (64B data + 16B pad).
// ===========================================================================
#define GSTG 40960                // Ah 10240 | Al 10240 | Bh 10240 | Bl 10240
#define G_AL 10240
#define G_BH 20480
#define G_BL 30720
#define ROWB 80
#define GSMEM_DYN (2 * GSTG)      // 81920 -> 2 CTAs/SM

template<int KD>
__device__ __forceinline__ void load_stage_g(
    uint32_t sb, const __nv_bfloat16* __restrict__ hi, const __nv_bfloat16* __restrict__ lo,
    int aBase, int bBase, int kt)
{
    int tid = threadIdx.x;
    #pragma unroll
    for (int p = 0; p < 2; p++) {
        int c = tid + p * 256;
        int row = c >> 2, ch = c & 3;
        size_t offA = (size_t)(aBase + row) * KD + kt + ch * 8;
        size_t offB = (size_t)(bBase + row) * KD + kt + ch * 8;
        uint32_t d = sb + row * ROWB + ch * 16;
        CP_ASYNC16(d,        hi + offA);
        CP_ASYNC16(d + G_AL, lo + offA);
        CP_ASYNC16(d + G_BH, hi + offB);
        CP_ASYNC16(d + G_BL, lo + offB);
    }
}

template<int KD>
__device__ __forceinline__ void gemm_mainloop(
    uint32_t sb, const __nv_bfloat16* hi, const __nv_bfloat16* lo,
    int aBase, int bBase, float acc[2][8][4])
{
    const int tid = threadIdx.x, wid = tid >> 5, lane = tid & 31;
    const int warpM = (wid & 3) * 32, warpN = (wid >> 2) * 64;
    const int aRow = lane & 15, aChunk = (lane >> 4) & 1;
    const int bRow = (lane & 7) | ((lane & 16) >> 1);
    const int bChunk = (lane >> 3) & 1;

    load_stage_g<KD>(sb, hi, lo, aBase, bBase, 0);
    CP_COMMIT();

    const int NK = KD / 32;
    for (int it = 0; it < NK; it++) {
        const int s = it & 1;
        if (it + 1 < NK) {
            load_stage_g<KD>(sb + (s ^ 1) * GSTG, hi, lo, aBase, bBase, (it + 1) * 32);
            CP_COMMIT();
            CP_WAIT1();
        } else {
            CP_WAIT0();
        }
        __syncthreads();

        const uint32_t Ab = sb + s * GSTG;
        const uint32_t Bb = Ab + G_BH;
        #pragma unroll
        for (int ks = 0; ks < 2; ks++) {
            uint32_t ah[2][4], al[2][4], bh[4][4], bl[4][4];
            uint32_t aAddr = Ab + (warpM + aRow) * ROWB + ks * 32 + aChunk * 16;
            LDSM4(ah[0], aAddr);
            LDSM4(ah[1], aAddr + 16 * ROWB);
            LDSM4(al[0], aAddr + G_AL);
            LDSM4(al[1], aAddr + G_AL + 16 * ROWB);
            uint32_t bAddr = Bb + (warpN + bRow) * ROWB + ks * 32 + bChunk * 16;
            #pragma unroll
            for (int nt = 0; nt < 4; nt++) {
                LDSM4(bh[nt], bAddr + nt * 16 * ROWB);
                LDSM4(bl[nt], bAddr + (G_BL - G_BH) + nt * 16 * ROWB);
            }
            #pragma unroll
            for (int mt = 0; mt < 2; mt++)
                #pragma unroll
                for (int j = 0; j < 8; j++)
                    MMA16816(acc[mt][j], ah[mt], bh[j >> 1][(j & 1) * 2], bh[j >> 1][(j & 1) * 2 + 1]);
            #pragma unroll
            for (int mt = 0; mt < 2; mt++)
                #pragma unroll
                for (int j = 0; j < 8; j++)
                    MMA16816(acc[mt][j], ah[mt], bl[j >> 1][(j & 1) * 2], bl[j >> 1][(j & 1) * 2 + 1]);
            #pragma unroll
            for (int mt = 0; mt < 2; mt++)
                #pragma unroll
                for (int j = 0; j < 8; j++)
                    MMA16816(acc[mt][j], al[mt], bh[j >> 1][(j & 1) * 2], bh[j >> 1][(j & 1) * 2 + 1]);
        }
        __syncthreads();
    }
}

// ===========================================================================
// fused GEMM kernel: blocks [0, NTILE) = dist tiles, [NTILE, 2*NTILE) = logits
// tiles. Same smem footprint both paths (80 KB dyn), 2 CTAs/SM. Logits tiles
// co-schedule into dist's stall windows and tail waves.
// ===========================================================================
__global__ void __launch_bounds__(256, 2) fused_gemm_kernel(float* __restrict__ out)
{
    extern __shared__ char smem[];
    uint32_t sb = smem_u32(smem);
    const int tid = threadIdx.x, wid = tid >> 5, lane = tid & 31;
    const int warpM = (wid & 3) * 32, warpN = (wid >> 2) * 64;
    __shared__ float sNi[128], sNj[128];

    float acc[2][8][4];
    #pragma unroll
    for (int m = 0; m < 2; m++)
        #pragma unroll
        for (int j = 0; j < 8; j++)
            #pragma unroll
            for (int q = 0; q < 4; q++) acc[m][j][q] = 0.f;

    if (blockIdx.x < NTILE) {
        // ------------------------- dist tile -------------------------
        int br, bc;
        tri_decode(blockIdx.x, br, bc);
        const int aBase = br * 128, bBase = bc * 128;

        gemm_mainloop<DF>(sb, &g_fhi[0], &g_flo[0], aBase, bBase, acc);

        if (tid < 128) sNi[tid] = g_fn[aBase + tid];
        else           sNj[tid - 128] = g_fn[bBase + tid - 128];
        __syncthreads();

        float* st = (float*)smem;   // [128][129]
        #pragma unroll
        for (int mt = 0; mt < 2; mt++) {
            const int r0 = warpM + mt * 16 + (lane >> 2);
            #pragma unroll
            for (int j = 0; j < 8; j++) {
                const int c0 = warpN + (j >> 1) * 16 + (j & 1) * 8 + 2 * (lane & 3);
                #pragma unroll
                for (int q = 0; q < 4; q++) {
                    const int rr = r0 + (q >> 1) * 8;
                    const int cc = c0 + (q & 1);
                    st[rr * 129 + cc] = fmaxf(sNi[rr] + sNj[cc] - 2.f * acc[mt][j][q], 0.f);
                }
            }
        }
        __syncthreads();

        for (int x = tid; x < 128 * 128; x += 256) {
            int mm = x >> 7, cc = x & 127;
            g_D[(size_t)(aBase + mm) * N2 + (bBase + cc)] = st[mm * 129 + cc];
        }
        if (bc > br) {
            for (int x = tid; x < 128 * 128; x += 256) {
                int rc = x >> 7, cm = x & 127;
                g_D[(size_t)(bBase + rc) * N2 + (aBase + cm)] = st[cm * 129 + rc];
            }
        }
    } else {
        // ------------------------- logits tile -------------------------
        int br, bc;
        tri_decode(blockIdx.x - NTILE, br, bc);
        const int aBase = br * 128, bBase = bc * 128;

        gemm_mainloop<DZ>(sb, &g_zhi[0], &g_zlo[0], aBase, bBase, acc);

        float* st = (float*)smem;
        #pragma unroll
        for (int mt = 0; mt < 2; mt++) {
            const int r0 = warpM + mt * 16 + (lane >> 2);
            #pragma unroll
            for (int j = 0; j < 8; j++) {
                const int c0 = warpN + (j >> 1) * 16 + (j & 1) * 8 + 2 * (lane & 3);
                #pragma unroll
                for (int q = 0; q < 4; q++)
                    st[(r0 + (q >> 1) * 8) * 129 + c0 + (q & 1)] = 2.f * acc[mt][j][q];
            }
        }
        __syncthreads();

        for (int x = tid; x < 128 * 128; x += 256) {
            int mm = x >> 7, cc = x & 127;
            int col = colmap(aBase + mm, bBase + cc);
            if (col >= 0) out[OUT_LOGITS + (size_t)(aBase + mm) * LCOLS + col] = st[mm * 129 + cc];
        }
        if (bc > br) {
            for (int x = tid; x < 128 * 128; x += 256) {
                int rc = x >> 7, cm = x & 127;
                int col = colmap(bBase + rc, aBase + cm);
                if (col >= 0) out[OUT_LOGITS + (size_t)(bBase + rc) * LCOLS + col] = st[cm * 129 + rc];
            }
        }
        __syncthreads();

        // fused exp + row/col softmax-denominator partials
        for (int x = tid; x < 128 * 128; x += 256) {
            int mm = x >> 7, cc = x & 127;
            float e = __expf(st[mm * 129 + cc]);
            if (br == bc && mm == cc) e = 0.f;     // exclude diagonal
            st[mm * 129 + cc] = e;
        }
        __syncthreads();

        {   // row sums -> slot bc, rows aBase..aBase+127 (2 threads per row)
            int row = tid >> 1, half = tid & 1;
            float s = 0.f;
            #pragma unroll 4
            for (int c2 = half * 64; c2 < half * 64 + 64; c2++) s += st[row * 129 + c2];
            s += __shfl_xor_sync(0xFFFFFFFFu, s, 1);
            if (half == 0) g_ls[(size_t)bc * N2 + aBase + row] = s;
        }
        if (bc > br) {   // col sums -> slot br, rows bBase..bBase+127
            int col = tid >> 1, half = tid & 1;
            float s = 0.f;
            #pragma unroll 4
            for (int r2 = half * 64; r2 < half * 64 + 64; r2++) s += st[r2 * 129 + col];
            s += __shfl_xor_sync(0xFFFFFFFFu, s, 1);
            if (half == 0) g_ls[(size_t)br * N2 + bBase + col] = s;
        }
    }
}

// ---------------------------------------------------------------------------
// loss_final: per row, S = sum of 64 partials; pos = 2*dot(z0n, z1n)
// ---------------------------------------------------------------------------
__global__ void __launch_bounds__(128) loss_final_kernel()
{
    int r = blockIdx.x, tid = threadIdx.x;
    int pr = (r < B4) ? r + B4 : r - B4;

    float a = (float)g_zhi[(size_t)r * DZ + tid] + (float)g_zlo[(size_t)r * DZ + tid];
    float b = (float)g_zhi[(size_t)pr * DZ + tid] + (float)g_zlo[(size_t)pr * DZ + tid];
    float p = a * b;
    float S = (tid < 64) ? g_ls[(size_t)tid * N2 + r] : 0.f;

    #pragma unroll
    for (int d = 16; d > 0; d >>= 1) {
        p += __shfl_xor_sync(0xFFFFFFFFu, p, d);
        S += __shfl_xor_sync(0xFFFFFFFFu, S, d);
    }
    __shared__ float sp[4], sS[4];
    if ((tid & 31) == 0) { sp[tid >> 5] = p; sS[tid >> 5] = S; }
    __syncthreads();
    if (tid == 0) {
        float P = sp[0] + sp[1] + sp[2] + sp[3];
        float SS = sS[0] + sS[1] + sS[2] + sS[3];
        g_lossper[r] = logf(SS) - 2.f * P;
    }
}

__global__ void __launch_bounds__(256) finalize_kernel(float* __restrict__ out)
{
    __shared__ double sred[256];
    int tid = threadIdx.x;
    double s = 0.0;
    for (int j = tid; j < N2; j += 256) s += (double)g_lossper[j];
    sred[tid] = s; __syncthreads();
    for (int st = 128; st > 0; st >>= 1) { if (tid < st) sred[tid] += sred[tid + st]; __syncthreads(); }
    if (tid == 0) out[OUT_LOSS] = (float)(sred[0] / (double)N2);
}

// ---------------------------------------------------------------------------
// LID: per row, exact radix-select (12/12/8-bit passes) of rank-32 / rank-512
// squared distance (self excluded), then LID sums. 512 threads.
// ---------------------------------------------------------------------------
__global__ void __launch_bounds__(512) select_kernel(float* __restrict__ out)
{
    int r = blockIdx.x, tid = threadIdx.x;
    __shared__ unsigned skey[N2];      // 32 KB
    __shared__ unsigned hist[4096];    // 16 KB
    __shared__ unsigned wtot[16];
    __shared__ unsigned s_bin;
    __shared__ int s_kk;
    __shared__ float sred[512];

    const float* drow = &g_D[(size_t)r * N2];
    for (int j = tid; j < N2; j += 512)
        skey[j] = (j == r) ? 0xFFFFFFFFu : __float_as_uint(drow[j]);
    __syncthreads();

    #pragma unroll
    for (int ksel = 0; ksel < 2; ksel++) {
        const int k = (ksel == 0) ? 32 : 512;
        int kk = k;
        unsigned prefixval = 0u;       // key >> pshift == prefixval
        int pshift = 32;

        #pragma unroll
        for (int pass = 0; pass < 3; pass++) {
            const int sh = (pass == 0) ? 20 : (pass == 1) ? 8 : 0;
            const unsigned bmask = (pass < 2) ? 4095u : 255u;

            #pragma unroll
            for (int b = 0; b < 8; b++) hist[tid + b * 512] = 0u;
            __syncthreads();

            for (int j = tid; j < N2; j += 512) {
                unsigned kv = skey[j];
                bool ok = (pshift >= 32) ? true : ((kv >> pshift) == prefixval);
                if (ok) atomicAdd(&hist[(kv >> sh) & bmask], 1u);
            }
            __syncthreads();

            // block scan: each thread owns 8 consecutive bins
            {
                unsigned tsum = 0;
                #pragma unroll
                for (int b = 0; b < 8; b++) tsum += hist[tid * 8 + b];
                unsigned v = tsum;
                #pragma unroll
                for (int d = 1; d < 32; d <<= 1) {
                    unsigned n = __shfl_up_sync(0xFFFFFFFFu, v, d);
                    if ((tid & 31) >= d) v += n;
                }
                if ((tid & 31) == 31) wtot[tid >> 5] = v;
                __syncthreads();
                if (tid < 16) {
                    unsigned t = wtot[tid];
                    #pragma unroll
                    for (int d = 1; d < 16; d <<= 1) {
                        unsigned n = __shfl_up_sync(0xFFFFu, t, d);
                        if (tid >= d) t += n;
                    }
                    wtot[tid] = t;
                }
                __syncthreads();
                unsigned incl = v + ((tid >= 32) ? wtot[(tid >> 5) - 1] : 0u);
                unsigned excl = incl - tsum;
                if ((unsigned)kk > excl && (unsigned)kk <= incl) {
                    unsigned cum = excl;
                    #pragma unroll
                    for (int b = 0; b < 8; b++) {
                        unsigned c = hist[tid * 8 + b];
                        if ((unsigned)kk <= cum + c) { s_bin = tid * 8 + b; s_kk = kk - (int)cum; break; }
                        cum += c;
                    }
                }
            }
            __syncthreads();
            prefixval = (prefixval << ((pass < 2) ? 12 : 8)) | s_bin;
            kk = s_kk;
            pshift = sh;
            __syncthreads();
        }

        const unsigned Kk = prefixval;               // exact k-th smallest key
        const float lnK = 0.5f * logf(__uint_as_float(Kk));
        float s = 0.f;
        for (int j = tid; j < N2; j += 512) {
            unsigned kv = skey[j];
            if (kv < Kk) s += 0.5f * logf(__uint_as_float(kv)) - lnK;
        }
        sred[tid] = s; __syncthreads();
        for (int st = 256; st > 0; st >>= 1) { if (tid < st) sred[tid] += sred[tid + st]; __syncthreads(); }
        if (tid == 0)
            out[(ksel == 0 ? OUT_LIDS32 : OUT_LIDS512) + r] = -(float)k / sred[0];
        __syncthreads();
    }
}

// ---------------------------------------------------------------------------
extern "C" void kernel_launch(void* const* d_in, const int* in_sizes, int n_in,
                              void* d_out, int out_size)
{
    const float* z0 = (const float*)d_in[0];
    const float* z1 = (const float*)d_in[1];
    const float* f0 = (const float*)d_in[2];
    const float* f1 = (const float*)d_in[3];
    float* out = (float*)d_out;

    cudaFuncSetAttribute(fused_gemm_kernel,
                         cudaFuncAttributeMaxDynamicSharedMemorySize, GSMEM_DYN);

    prep_kernel<<<N2, 256>>>(z0, z1, f0, f1, out);
    fused_gemm_kernel<<<2 * NTILE, 256, GSMEM_DYN>>>(out);
    select_kernel<<<N2, 512>>>(out);
    loss_final_kernel<<<N2, 128>>>();
    finalize_kernel<<<1, 256>>>(out);
}